// round 3
// baseline (speedup 1.0000x reference)
#include <cuda_runtime.h>

#define HDIM 10
#define MM   41
#define SMAX 512

typedef unsigned long long u64;

// Packed tables (written by repack_kernel each launch; deterministic).
__device__ float4 g_W1p[SMAX * HDIM];   // [s][p*2+q] = (wx[2p],wx[2p+1],wy[2p],wy[2p+1]) pol q
__device__ float4 g_meta[SMAX];         // (Cx, Cy, Cy, -Cx)  -> mc.x=(Cx,Cy), mc.y=(Cy,-Cx)
__device__ int    g_pk[SMAX];           // (c+m) | (c+m+n)<<8 | (c+n)<<16
__device__ float4 g_W2p[MM * HDIM];

__device__ __forceinline__ u64 pk2(float a, float b) {
    u64 r; asm("mov.b64 %0,{%1,%2};" : "=l"(r) : "f"(a), "f"(b)); return r;
}
__device__ __forceinline__ void up2(u64 v, float& a, float& b) {
    asm("mov.b64 {%0,%1},%2;" : "=f"(a), "=f"(b) : "l"(v));
}
__device__ __forceinline__ void fma2(u64& d, u64 a, u64 b) {
    asm("fma.rn.f32x2 %0,%1,%2,%0;" : "+l"(d) : "l"(a), "l"(b));
}
__device__ __forceinline__ void add2(u64& d, u64 a) {
    asm("add.rn.f32x2 %0,%1,%0;" : "+l"(d) : "l"(a));
}

__global__ void repack_kernel(const float2* __restrict__ W1,
                              const float2* __restrict__ W2,
                              const float2* __restrict__ C,
                              const int* __restrict__ m_idx,
                              const int* __restrict__ n_idx,
                              int S) {
    int t = blockIdx.x * blockDim.x + threadIdx.x;
    if (t < S) {
#pragma unroll
        for (int p = 0; p < 5; p++)
#pragma unroll
            for (int q = 0; q < 2; q++) {
                float2 wa = W1[((2 * p) * 2 + q) * S + t];
                float2 wb = W1[((2 * p + 1) * 2 + q) * S + t];
                g_W1p[t * 10 + p * 2 + q] = make_float4(wa.x, wb.x, wa.y, wb.y);
            }
        float2 cc = C[t];
        g_meta[t] = make_float4(cc.x, cc.y, cc.y, -cc.x);
        const int c = MM / 2;
        int m = m_idx[t], n = n_idx[t];
        g_pk[t] = (c + m) | ((c + m + n) << 8) | ((c + n) << 16);
    }
    if (t < MM) {
#pragma unroll
        for (int p = 0; p < 5; p++)
#pragma unroll
            for (int q = 0; q < 2; q++) {
                float2 wa = W2[((2 * p) * 2 + q) * MM + t];
                float2 wb = W2[((2 * p + 1) * 2 + q) * MM + t];
                g_W2p[t * 10 + p * 2 + q] = make_float4(wa.x, wb.x, wa.y, wb.y);
            }
    }
}

// Block = 32 batch elements, 8 warps; lane == local batch element.
// Warps split the s-range (and k-range) 8 ways; serial smem RMW reductions.
__global__ __launch_bounds__(256, 3)
void eq_main(const float4* __restrict__ x,      // [B][41] (E0r,E0i,E1r,E1i)
             const float* __restrict__ task,    // [B][4]
             const float2* __restrict__ b1,     // [10]
             const float2* __restrict__ b2,     // [10]
             float4* __restrict__ out,          // [B]
             int S) {
    __shared__ float4 E_sh[32 * 41];            // 21 KB, stride 41 (odd -> conflict-free)
    __shared__ u64 bbuf[20 * 32];               // 5 KB  reduced B accumulators
    __shared__ u64 abuf[22 * 32];               // 5.6 KB A/P reduction buffer

    const int lane = threadIdx.x & 31;
    const int warp = threadIdx.x >> 5;
    const int b0 = blockIdx.x * 32;

    for (int bl = warp; bl < 32; bl += 8)
        for (int k = lane; k < MM; k += 32)
            E_sh[bl * 41 + k] = x[(size_t)(b0 + bl) * MM + k];
    __syncthreads();

    const float4* Eb = &E_sh[lane * 41];

    // ================= W2 phase (registers die before the s-loop) =================
    {
        u64 aB[20];
#pragma unroll
        for (int i = 0; i < 20; i++) aB[i] = 0ull;

        for (int k = warp; k < MM; k += 8) {
            float4 Ek = Eb[k];
            u64 E0xb = pk2(Ek.x, Ek.x), E0yb = pk2(Ek.y, Ek.y), E0ynb = pk2(-Ek.y, -Ek.y);
            u64 E1xb = pk2(Ek.z, Ek.z), E1yb = pk2(Ek.w, Ek.w), E1ynb = pk2(-Ek.w, -Ek.w);
            const ulonglong2* wr = (const ulonglong2*)&g_W2p[k * 10];
#pragma unroll
            for (int p = 0; p < 5; p++) {
                ulonglong2 u0 = wr[2 * p];
                ulonglong2 u1 = wr[2 * p + 1];
                fma2(aB[p],      u0.x, E0xb); fma2(aB[p],      u0.y, E0ynb);
                fma2(aB[p],      u1.x, E1xb); fma2(aB[p],      u1.y, E1ynb);
                fma2(aB[5 + p],  u0.x, E0yb); fma2(aB[5 + p],  u0.y, E0xb);
                fma2(aB[5 + p],  u1.x, E1yb); fma2(aB[5 + p],  u1.y, E1xb);
                fma2(aB[10 + p], u0.x, E1xb); fma2(aB[10 + p], u0.y, E1ynb);
                fma2(aB[10 + p], u1.x, E0xb); fma2(aB[10 + p], u1.y, E0ynb);
                fma2(aB[15 + p], u0.x, E1yb); fma2(aB[15 + p], u0.y, E1xb);
                fma2(aB[15 + p], u1.x, E0yb); fma2(aB[15 + p], u1.y, E0xb);
            }
        }
        // serial RMW reduction into bbuf
        if (warp == 0) {
#pragma unroll
            for (int i = 0; i < 20; i++) bbuf[i * 32 + lane] = aB[i];
        }
        __syncthreads();
        for (int w = 1; w < 8; w++) {
            if (warp == w) {
#pragma unroll
                for (int i = 0; i < 20; i++) {
                    u64 v = bbuf[i * 32 + lane];
                    add2(v, aB[i]);
                    bbuf[i * 32 + lane] = v;
                }
            }
            __syncthreads();
        }
    }

    // ================= hot s-loop =================
    u64 aA[20];
    u64 aP0 = 0ull, aP1 = 0ull;
#pragma unroll
    for (int i = 0; i < 20; i++) aA[i] = 0ull;

    for (int s = warp; s < S; s += 8) {
        const ulonglong2 mc = *(const ulonglong2*)&g_meta[s];
        const int pk = g_pk[s];
        float4 Em  = Eb[pk & 255];
        float4 Emn = Eb[(pk >> 8) & 255];
        float4 En  = Eb[(pk >> 16) & 255];
        float Asx = Em.x * Emn.x + Em.y * Emn.y + Em.z * Emn.z + Em.w * Emn.w;
        float Asy = Em.y * Emn.x - Em.x * Emn.y + Em.w * Emn.z - Em.z * Emn.w;
        float F0x = Asx * En.x - Asy * En.y, F0y = Asx * En.y + Asy * En.x;
        float F1x = Asx * En.z - Asy * En.w, F1y = Asx * En.w + Asy * En.z;

        u64 F0xb = pk2(F0x, F0x), F0yb = pk2(F0y, F0y), F0ynb = pk2(-F0y, -F0y);
        u64 F1xb = pk2(F1x, F1x), F1yb = pk2(F1y, F1y), F1ynb = pk2(-F1y, -F1y);

        // pbc: (Cx,Cy)*(Fx,Fx) + (Cy,-Cx)*(-Fy,-Fy) = (CxFx - CyFy, CyFx + CxFy)
        fma2(aP0, mc.x, F0xb); fma2(aP0, mc.y, F0ynb);
        fma2(aP1, mc.x, F1xb); fma2(aP1, mc.y, F1ynb);

        const ulonglong2* wr = (const ulonglong2*)&g_W1p[s * 10];
#pragma unroll
        for (int p = 0; p < 5; p++) {
            ulonglong2 u0 = wr[2 * p];
            ulonglong2 u1 = wr[2 * p + 1];
            fma2(aA[p],      u0.x, F0xb); fma2(aA[p],      u0.y, F0ynb);
            fma2(aA[p],      u1.x, F1xb); fma2(aA[p],      u1.y, F1ynb);
            fma2(aA[5 + p],  u0.x, F0yb); fma2(aA[5 + p],  u0.y, F0xb);
            fma2(aA[5 + p],  u1.x, F1yb); fma2(aA[5 + p],  u1.y, F1xb);
            fma2(aA[10 + p], u0.x, F1xb); fma2(aA[10 + p], u0.y, F1ynb);
            fma2(aA[10 + p], u1.x, F0xb); fma2(aA[10 + p], u1.y, F0ynb);
            fma2(aA[15 + p], u0.x, F1yb); fma2(aA[15 + p], u0.y, F1xb);
            fma2(aA[15 + p], u1.x, F0yb); fma2(aA[15 + p], u1.y, F0xb);
        }
    }

    // ================= A/P reduction (serial RMW) =================
    if (warp == 1) {
#pragma unroll
        for (int i = 0; i < 20; i++) abuf[i * 32 + lane] = aA[i];
        abuf[20 * 32 + lane] = aP0;
        abuf[21 * 32 + lane] = aP1;
    }
    __syncthreads();
    for (int w = 2; w < 8; w++) {
        if (warp == w) {
#pragma unroll
            for (int i = 0; i < 20; i++) {
                u64 v = abuf[i * 32 + lane];
                add2(v, aA[i]);
                abuf[i * 32 + lane] = v;
            }
            u64 v = abuf[20 * 32 + lane]; add2(v, aP0); abuf[20 * 32 + lane] = v;
            v = abuf[21 * 32 + lane];     add2(v, aP1); abuf[21 * 32 + lane] = v;
        }
        __syncthreads();
    }

    if (warp == 0) {
#pragma unroll
        for (int i = 0; i < 20; i++) add2(aA[i], abuf[i * 32 + lane]);
        add2(aP0, abuf[20 * 32 + lane]);
        add2(aP1, abuf[21 * 32 + lane]);

        float P0x, P0y, P1x, P1y;
        up2(aP0, P0x, P0y);
        up2(aP1, P1x, P1y);

        float p = exp10f(task[(size_t)(b0 + lane) * 4] * 0.1f) * 0.5f;
        float4 Ec = Eb[MM / 2];
        float o0x = Ec.x + p * P0x, o0y = Ec.y + p * P0y;
        float o1x = Ec.z + p * P1x, o1y = Ec.w + p * P1y;

        float t0x = 0.f, t0y = 0.f, t1x = 0.f, t1y = 0.f;
#pragma unroll
        for (int pp = 0; pp < 5; pp++) {
            float A0x[2], A0y[2], A1x[2], A1y[2];
            float Bx0[2], By0[2], Bx1[2], By1[2];
            up2(aA[pp],      A0x[0], A0x[1]);
            up2(aA[5 + pp],  A0y[0], A0y[1]);
            up2(aA[10 + pp], A1x[0], A1x[1]);
            up2(aA[15 + pp], A1y[0], A1y[1]);
            up2(bbuf[pp * 32 + lane],        Bx0[0], Bx0[1]);
            up2(bbuf[(5 + pp) * 32 + lane],  By0[0], By0[1]);
            up2(bbuf[(10 + pp) * 32 + lane], Bx1[0], Bx1[1]);
            up2(bbuf[(15 + pp) * 32 + lane], By1[0], By1[1]);
#pragma unroll
            for (int h = 0; h < 2; h++) {
                int o = 2 * pp + h;
                float2 c1 = b1[o], c2 = b2[o];
                float a0x = A0x[h] + c1.x, a0y = A0y[h] + c1.y;
                float a1x = A1x[h] + c1.x, a1y = A1y[h] + c1.y;
                float bx0 = Bx0[h] + c2.x, by0 = By0[h] + c2.y;
                float bx1 = Bx1[h] + c2.x, by1 = By1[h] + c2.y;
                float n0 = bx0 * bx0 + by0 * by0;
                float sx0 = bx0 * bx0 - by0 * by0, sy0 = 2.f * bx0 * by0;
                t0x += a0x * n0 + a0x * sx0 + a0y * sy0;
                t0y += a0y * n0 + a0x * sy0 - a0y * sx0;
                float n1 = bx1 * bx1 + by1 * by1;
                float sx1 = bx1 * bx1 - by1 * by1, sy1 = 2.f * bx1 * by1;
                t1x += a1x * n1 + a1x * sx1 + a1y * sy1;
                t1y += a1y * n1 + a1x * sy1 - a1y * sx1;
            }
        }
        float sc = 3.1622776601683794e-5f * p * p;   // (1e-4/sqrt(HDIM)) * P^2
        out[b0 + lane] = make_float4(o0x + sc * t0x, o0y + sc * t0y,
                                     o1x + sc * t1x, o1y + sc * t1y);
    }
}

extern "C" void kernel_launch(void* const* d_in, const int* in_sizes, int n_in,
                              void* d_out, int out_size) {
    const float4* x    = (const float4*)d_in[0];
    const float*  task = (const float*)d_in[1];
    const float2* C    = (const float2*)d_in[2];
    const float2* W1   = (const float2*)d_in[3];
    const float2* b1   = (const float2*)d_in[4];
    const float2* W2   = (const float2*)d_in[5];
    const float2* b2   = (const float2*)d_in[6];
    const int* m_idx   = (const int*)d_in[7];
    const int* n_idx   = (const int*)d_in[8];

    int S = in_sizes[8];
    int B = in_sizes[1] / 4;

    repack_kernel<<<(S + 127) / 128, 128>>>(W1, W2, C, m_idx, n_idx, S);
    eq_main<<<B / 32, 256>>>(x, task, b1, b2, (float4*)d_out, S);
}

// round 4
// speedup vs baseline: 1.7238x; 1.7238x over previous
#include <cuda_runtime.h>

#define HDIM 10
#define MM   41
#define SMAX 512

typedef unsigned long long u64;

// Packed tables (repacked every launch; deterministic).
// Per s: 5 pairs p, each pair has ws = (Wsx[2p],Wsx[2p+1],Wsy[2p],Wsy[2p+1])
// and wd likewise, where Ws = (W1[o,pol0]+W1[o,pol1])/2, Wd = (W1[o,pol0]-W1[o,pol1])/2.
__device__ float4 g_W1p[SMAX * HDIM];   // [s*10 + 2p] = ws, [s*10 + 2p + 1] = wd
__device__ float4 g_meta[SMAX];         // (Cx/2, Cy/2, -Cy/2, pk_bits)
__device__ float4 g_W2p[MM * HDIM];     // same S/D packing for W2

__device__ __forceinline__ u64 pk2(float a, float b) {
    u64 r; asm("mov.b64 %0,{%1,%2};" : "=l"(r) : "f"(a), "f"(b)); return r;
}
__device__ __forceinline__ void up2(u64 v, float& a, float& b) {
    asm("mov.b64 {%0,%1},%2;" : "=f"(a), "=f"(b) : "l"(v));
}
__device__ __forceinline__ void fma2(u64& d, u64 a, u64 b) {
    asm("fma.rn.f32x2 %0,%1,%2,%0;" : "+l"(d) : "l"(a), "l"(b));
}
__device__ __forceinline__ void add2(u64& d, u64 a) {
    asm("add.rn.f32x2 %0,%1,%0;" : "+l"(d) : "l"(a));
}

__global__ void repack_kernel(const float2* __restrict__ W1,
                              const float2* __restrict__ W2,
                              const float2* __restrict__ C,
                              const int* __restrict__ m_idx,
                              const int* __restrict__ n_idx,
                              int S) {
    int t = blockIdx.x * blockDim.x + threadIdx.x;
    if (t < S) {
#pragma unroll
        for (int p = 0; p < 5; p++) {
            float2 a0 = W1[((2 * p) * 2 + 0) * S + t];      // o=2p, pol0
            float2 a1 = W1[((2 * p) * 2 + 1) * S + t];      // o=2p, pol1
            float2 b0c = W1[((2 * p + 1) * 2 + 0) * S + t]; // o=2p+1, pol0
            float2 b1c = W1[((2 * p + 1) * 2 + 1) * S + t];
            float2 sa = make_float2(0.5f * (a0.x + a1.x), 0.5f * (a0.y + a1.y));
            float2 da = make_float2(0.5f * (a0.x - a1.x), 0.5f * (a0.y - a1.y));
            float2 sb = make_float2(0.5f * (b0c.x + b1c.x), 0.5f * (b0c.y + b1c.y));
            float2 db = make_float2(0.5f * (b0c.x - b1c.x), 0.5f * (b0c.y - b1c.y));
            g_W1p[t * 10 + 2 * p]     = make_float4(sa.x, sb.x, sa.y, sb.y);
            g_W1p[t * 10 + 2 * p + 1] = make_float4(da.x, db.x, da.y, db.y);
        }
        float2 cc = C[t];
        const int c = MM / 2;
        int m = m_idx[t], n = n_idx[t];
        int pk = (c + m) | ((c + m + n) << 8) | ((c + n) << 16);
        g_meta[t] = make_float4(0.5f * cc.x, 0.5f * cc.y, -0.5f * cc.y, __int_as_float(pk));
    }
    if (t < MM) {
#pragma unroll
        for (int p = 0; p < 5; p++) {
            float2 a0 = W2[((2 * p) * 2 + 0) * MM + t];
            float2 a1 = W2[((2 * p) * 2 + 1) * MM + t];
            float2 b0c = W2[((2 * p + 1) * 2 + 0) * MM + t];
            float2 b1c = W2[((2 * p + 1) * 2 + 1) * MM + t];
            float2 sa = make_float2(0.5f * (a0.x + a1.x), 0.5f * (a0.y + a1.y));
            float2 da = make_float2(0.5f * (a0.x - a1.x), 0.5f * (a0.y - a1.y));
            float2 sb = make_float2(0.5f * (b0c.x + b1c.x), 0.5f * (b0c.y + b1c.y));
            float2 db = make_float2(0.5f * (b0c.x - b1c.x), 0.5f * (b0c.y - b1c.y));
            g_W2p[t * 10 + 2 * p]     = make_float4(sa.x, sb.x, sa.y, sb.y);
            g_W2p[t * 10 + 2 * p + 1] = make_float4(da.x, db.x, da.y, db.y);
        }
    }
}

// Block = 32 batch elements, 4 warps; lane == local batch element.
__global__ __launch_bounds__(128, 4)
void eq_main(const float4* __restrict__ x,      // [B][41] (E0r,E0i,E1r,E1i)
             const float* __restrict__ task,    // [B][4]
             const float2* __restrict__ b1,     // [10]
             const float2* __restrict__ b2,     // [10]
             float4* __restrict__ out,          // [B]
             int S) {
    __shared__ float4 E_sh[32 * 41];            // 21 KB (odd stride -> conflict-free)
    __shared__ u64 red[2][44][32];              // 22.5 KB

    const int lane = threadIdx.x & 31;
    const int warp = threadIdx.x >> 5;
    const int b0 = blockIdx.x * 32;

    for (int bl = warp; bl < 32; bl += 4)
        for (int k = lane; k < MM; k += 32)
            E_sh[bl * 41 + k] = x[(size_t)(b0 + bl) * MM + k];
    __syncthreads();

    const float4* Eb = &E_sh[lane * 41];

    // acc layout: [0..4]=Sx, [5..9]=Sy, [10..14]=Dx, [15..19]=Dy
    u64 aA[20];
    u64 aPS = 0ull, aPD = 0ull;
#pragma unroll
    for (int i = 0; i < 20; i++) aA[i] = 0ull;

#pragma unroll 2
    for (int s = warp; s < S; s += 4) {
        float4 meta = g_meta[s];
        const int pk = __float_as_int(meta.w);
        float4 Em  = Eb[pk & 255];
        float4 Emn = Eb[(pk >> 8) & 255];
        float4 En  = Eb[(pk >> 16) & 255];
        // Asum = sum_p E[c+m,p] * conj(E[c+m+n,p])
        float Asx = Em.x * Emn.x + Em.y * Emn.y + Em.z * Emn.z + Em.w * Emn.w;
        float Asy = Em.y * Emn.x - Em.x * Emn.y + Em.w * Emn.z - Em.z * Emn.w;
        // Fs = As*(En0+En1), Fd = As*(En0-En1)
        float Ensx = En.x + En.z, Ensy = En.y + En.w;
        float Endx = En.x - En.z, Endy = En.y - En.w;
        float Fsx = Asx * Ensx - Asy * Ensy, Fsy = Asx * Ensy + Asy * Ensx;
        float Fdx = Asx * Endx - Asy * Endy, Fdy = Asx * Endy + Asy * Endx;

        u64 Fsxb = pk2(Fsx, Fsx), Fsyb = pk2(Fsy, Fsy), Fsynb = pk2(-Fsy, -Fsy);
        u64 Fdxb = pk2(Fdx, Fdx), Fdyb = pk2(Fdy, Fdy), Fdynb = pk2(-Fdy, -Fdy);

        // pbc halves: PS += C*Fs, PD += C*Fd (C pre-halved)
        u64 mc1 = pk2(meta.x, meta.y);   // (Cx, Cy)
        u64 mc2 = pk2(meta.z, meta.x);   // (-Cy, Cx)
        fma2(aPS, mc1, Fsxb); fma2(aPS, mc2, Fsyb);
        fma2(aPD, mc1, Fdxb); fma2(aPD, mc2, Fdyb);

        const ulonglong2* wr = (const ulonglong2*)&g_W1p[s * 10];
#pragma unroll
        for (int p = 0; p < 5; p++) {
            ulonglong2 us = wr[2 * p];       // (wsx2 | wsy2)
            ulonglong2 ud = wr[2 * p + 1];   // (wdx2 | wdy2)
            fma2(aA[p],      us.x, Fsxb); fma2(aA[p],      us.y, Fsynb);
            fma2(aA[5 + p],  us.x, Fsyb); fma2(aA[5 + p],  us.y, Fsxb);
            fma2(aA[10 + p], ud.x, Fdxb); fma2(aA[10 + p], ud.y, Fdynb);
            fma2(aA[15 + p], ud.x, Fdyb); fma2(aA[15 + p], ud.y, Fdxb);
        }
    }

    // ---- W2 conv (S/D form) ----
    u64 aB[20];
#pragma unroll
    for (int i = 0; i < 20; i++) aB[i] = 0ull;

    for (int k = warp; k < MM; k += 4) {
        float4 Ek = Eb[k];
        float Esx = Ek.x + Ek.z, Esy = Ek.y + Ek.w;
        float Edx = Ek.x - Ek.z, Edy = Ek.y - Ek.w;
        u64 Esxb = pk2(Esx, Esx), Esyb = pk2(Esy, Esy), Esynb = pk2(-Esy, -Esy);
        u64 Edxb = pk2(Edx, Edx), Edyb = pk2(Edy, Edy), Edynb = pk2(-Edy, -Edy);
        const ulonglong2* wr = (const ulonglong2*)&g_W2p[k * 10];
#pragma unroll
        for (int p = 0; p < 5; p++) {
            ulonglong2 us = wr[2 * p];
            ulonglong2 ud = wr[2 * p + 1];
            fma2(aB[p],      us.x, Esxb); fma2(aB[p],      us.y, Esynb);
            fma2(aB[5 + p],  us.x, Esyb); fma2(aB[5 + p],  us.y, Esxb);
            fma2(aB[10 + p], ud.x, Edxb); fma2(aB[10 + p], ud.y, Edynb);
            fma2(aB[15 + p], ud.x, Edyb); fma2(aB[15 + p], ud.y, Edxb);
        }
    }

    // ---- 4->2->1 tree reduction across warps ----
    if (warp >= 2) {
        u64* q = &red[warp - 2][0][lane];
#pragma unroll
        for (int i = 0; i < 20; i++) { q[i * 32] = aA[i]; q[(20 + i) * 32] = aB[i]; }
        q[40 * 32] = aPS; q[41 * 32] = aPD;
    }
    __syncthreads();
    if (warp < 2) {
        const u64* q = &red[warp][0][lane];
#pragma unroll
        for (int i = 0; i < 20; i++) { add2(aA[i], q[i * 32]); add2(aB[i], q[(20 + i) * 32]); }
        add2(aPS, q[40 * 32]); add2(aPD, q[41 * 32]);
    }
    __syncthreads();
    if (warp == 1) {
        u64* q = &red[0][0][lane];
#pragma unroll
        for (int i = 0; i < 20; i++) { q[i * 32] = aA[i]; q[(20 + i) * 32] = aB[i]; }
        q[40 * 32] = aPS; q[41 * 32] = aPD;
    }
    __syncthreads();

    if (warp == 0) {
        const u64* q = &red[0][0][lane];
#pragma unroll
        for (int i = 0; i < 20; i++) { add2(aA[i], q[i * 32]); add2(aB[i], q[(20 + i) * 32]); }
        add2(aPS, q[40 * 32]); add2(aPD, q[41 * 32]);

        float PSx, PSy, PDx, PDy;
        up2(aPS, PSx, PSy);
        up2(aPD, PDx, PDy);
        float P0x = PSx + PDx, P0y = PSy + PDy;
        float P1x = PSx - PDx, P1y = PSy - PDy;

        float p = exp10f(task[(size_t)(b0 + lane) * 4] * 0.1f) * 0.5f;
        float4 Ec = Eb[MM / 2];
        float o0x = Ec.x + p * P0x, o0y = Ec.y + p * P0y;
        float o1x = Ec.z + p * P1x, o1y = Ec.w + p * P1y;

        float t0x = 0.f, t0y = 0.f, t1x = 0.f, t1y = 0.f;
#pragma unroll
        for (int pp = 0; pp < 5; pp++) {
            float Sx[2], Sy[2], Dx[2], Dy[2];
            float bSx[2], bSy[2], bDx[2], bDy[2];
            up2(aA[pp],      Sx[0], Sx[1]);
            up2(aA[5 + pp],  Sy[0], Sy[1]);
            up2(aA[10 + pp], Dx[0], Dx[1]);
            up2(aA[15 + pp], Dy[0], Dy[1]);
            up2(aB[pp],      bSx[0], bSx[1]);
            up2(aB[5 + pp],  bSy[0], bSy[1]);
            up2(aB[10 + pp], bDx[0], bDx[1]);
            up2(aB[15 + pp], bDy[0], bDy[1]);
#pragma unroll
            for (int h = 0; h < 2; h++) {
                int o = 2 * pp + h;
                float2 c1 = b1[o], c2 = b2[o];
                float a0x = Sx[h] + Dx[h] + c1.x, a0y = Sy[h] + Dy[h] + c1.y;
                float a1x = Sx[h] - Dx[h] + c1.x, a1y = Sy[h] - Dy[h] + c1.y;
                float bx0 = bSx[h] + bDx[h] + c2.x, by0 = bSy[h] + bDy[h] + c2.y;
                float bx1 = bSx[h] - bDx[h] + c2.x, by1 = bSy[h] - bDy[h] + c2.y;
                float n0 = bx0 * bx0 + by0 * by0;
                float sx0 = bx0 * bx0 - by0 * by0, sy0 = 2.f * bx0 * by0;
                t0x += a0x * n0 + a0x * sx0 + a0y * sy0;
                t0y += a0y * n0 + a0x * sy0 - a0y * sx0;
                float n1 = bx1 * bx1 + by1 * by1;
                float sx1 = bx1 * bx1 - by1 * by1, sy1 = 2.f * bx1 * by1;
                t1x += a1x * n1 + a1x * sx1 + a1y * sy1;
                t1y += a1y * n1 + a1x * sy1 - a1y * sx1;
            }
        }
        float sc = 3.1622776601683794e-5f * p * p;   // (1e-4/sqrt(HDIM)) * P^2
        out[b0 + lane] = make_float4(o0x + sc * t0x, o0y + sc * t0y,
                                     o1x + sc * t1x, o1y + sc * t1y);
    }
}

extern "C" void kernel_launch(void* const* d_in, const int* in_sizes, int n_in,
                              void* d_out, int out_size) {
    const float4* x    = (const float4*)d_in[0];
    const float*  task = (const float*)d_in[1];
    const float2* C    = (const float2*)d_in[2];
    const float2* W1   = (const float2*)d_in[3];
    const float2* b1   = (const float2*)d_in[4];
    const float2* W2   = (const float2*)d_in[5];
    const float2* b2   = (const float2*)d_in[6];
    const int* m_idx   = (const int*)d_in[7];
    const int* n_idx   = (const int*)d_in[8];

    int S = in_sizes[8];
    int B = in_sizes[1] / 4;

    repack_kernel<<<(S + 127) / 128, 128>>>(W1, W2, C, m_idx, n_idx, S);
    eq_main<<<B / 32, 128>>>(x, task, b1, b2, (float4*)d_out, S);
}